// round 3
// baseline (speedup 1.0000x reference)
#include <cuda_runtime.h>

#define NEG 0.2f
#define MAXN 100000
#define MAXE 1600000
#define MAXET (MAXN + MAXE)

// ---------------- scratch (static __device__ = allowed, no allocs) ----------
__device__ int   g_src[MAXET];
__device__ int   g_dst[MAXET];
__device__ float g_h1  [(size_t)MAXN * 128];
__device__ float g_agg1[(size_t)MAXN * 128];
__device__ float g_als1[MAXN * 4];
__device__ float g_ald1[MAXN * 4];
__device__ float g_den1[MAXN * 4];
__device__ float g_h2  [MAXN * 16];
__device__ float g_als2[MAXN];
__device__ float g_ald2[MAXN];
__device__ float g_den2[MAXN];

// ---------------- helpers ---------------------------------------------------
__device__ __forceinline__ float lexp(float e) {
    e = e > 0.f ? e : NEG * e;       // LeakyReLU(0.2)
    return __expf(e);                // softmax shift-invariant -> no max pass
}

__device__ __forceinline__ void red_add_v4(float* p, float4 v) {
    asm volatile("red.global.add.v4.f32 [%0], {%1,%2,%3,%4};"
                 :: "l"(p), "f"(v.x), "f"(v.y), "f"(v.z), "f"(v.w) : "memory");
}
__device__ __forceinline__ void red_add_f(float* p, float v) {
    asm volatile("red.global.add.f32 [%0], %1;" :: "l"(p), "f"(v) : "memory");
}

// ---------------- k0: edge list int32 -> scratch (+self loops) --------------
__global__ void k_prep(const int* __restrict__ ei, int E, int ET) {
    int i = blockIdx.x * blockDim.x + threadIdx.x;
    if (i >= ET) return;
    int s, d;
    if (i < E) { s = ei[i]; d = ei[E + i]; }
    else       { s = d = i - E; }
    g_src[i] = s;
    g_dst[i] = d;
}

// ---------------- k1: zero accumulators -------------------------------------
__global__ void k_init(float* __restrict__ out, int N) {
    int i = blockIdx.x * blockDim.x + threadIdx.x;
    int n128 = N * 128;
    if (i < n128)   g_agg1[i] = 0.f;
    if (i < N * 16) out[i]    = 0.f;
    if (i < N * 4)  g_den1[i] = 0.f;
    if (i < N)      g_den2[i] = 0.f;
}

// ---------------- k2: GEMM1 (x @ W1) + attention logits, fused --------------
// 64 rows x 128 cols per block, 256 threads, thread = 8 rows x 4 cols.
#define G1_ROWS 64
__global__ void __launch_bounds__(256)
k_gemm1(const float* __restrict__ x, const float* __restrict__ W1,
        const float* __restrict__ a_src1, const float* __restrict__ a_dst1,
        int n) {
    extern __shared__ float sm[];
    float* Ws = sm;                                  // [128][128]
    float (*xs)[128] = (float(*)[128])(sm + 128 * 128);  // [64][128]
    __shared__ float s_as[128], s_ad[128];
    __shared__ float s_als[G1_ROWS][4], s_ald[G1_ROWS][4];

    int t = threadIdx.x;
    int row0 = blockIdx.x * G1_ROWS;

    for (int i = t; i < 128 * 128 / 4; i += 256)
        ((float4*)Ws)[i] = ((const float4*)W1)[i];
    if (t < 128) { s_as[t] = a_src1[t]; s_ad[t] = a_dst1[t]; }
    if (t < G1_ROWS * 4) { ((float*)s_als)[t] = 0.f; ((float*)s_ald)[t] = 0.f; }
    for (int i = t; i < G1_ROWS * 32; i += 256) {
        int r = i >> 5, kq = i & 31;
        int row = row0 + r;
        float4 v = (row < n) ? ((const float4*)x)[(size_t)row * 32 + kq]
                             : make_float4(0.f, 0.f, 0.f, 0.f);
        ((float4*)xs[r])[kq] = v;
    }
    __syncthreads();

    const int c0 = (t & 31) * 4;
    const int r0 = (t >> 5) * 8;
    float acc[8][4];
#pragma unroll
    for (int r = 0; r < 8; r++)
#pragma unroll
        for (int c = 0; c < 4; c++) acc[r][c] = 0.f;

#pragma unroll 4
    for (int k = 0; k < 128; k += 4) {
        float4 w0 = *(const float4*)&Ws[(k + 0) * 128 + c0];
        float4 w1 = *(const float4*)&Ws[(k + 1) * 128 + c0];
        float4 w2 = *(const float4*)&Ws[(k + 2) * 128 + c0];
        float4 w3 = *(const float4*)&Ws[(k + 3) * 128 + c0];
#pragma unroll
        for (int r = 0; r < 8; r++) {
            float4 xv = *(const float4*)&xs[r0 + r][k];
            acc[r][0] += xv.x * w0.x + xv.y * w1.x + xv.z * w2.x + xv.w * w3.x;
            acc[r][1] += xv.x * w0.y + xv.y * w1.y + xv.z * w2.y + xv.w * w3.y;
            acc[r][2] += xv.x * w0.z + xv.y * w1.z + xv.z * w2.z + xv.w * w3.z;
            acc[r][3] += xv.x * w0.w + xv.y * w1.w + xv.z * w2.w + xv.w * w3.w;
        }
    }

    const int head = c0 >> 5;
#pragma unroll
    for (int r = 0; r < 8; r++) {
        int row = row0 + r0 + r;
        if (row < n) {
            *(float4*)&g_h1[(size_t)row * 128 + c0] =
                make_float4(acc[r][0], acc[r][1], acc[r][2], acc[r][3]);
            float ps = acc[r][0] * s_as[c0]     + acc[r][1] * s_as[c0 + 1]
                     + acc[r][2] * s_as[c0 + 2] + acc[r][3] * s_as[c0 + 3];
            float pd = acc[r][0] * s_ad[c0]     + acc[r][1] * s_ad[c0 + 1]
                     + acc[r][2] * s_ad[c0 + 2] + acc[r][3] * s_ad[c0 + 3];
            atomicAdd(&s_als[r0 + r][head], ps);
            atomicAdd(&s_ald[r0 + r][head], pd);
        }
    }
    __syncthreads();
    if (t < G1_ROWS * 4) {
        int r = t >> 2, hh = t & 3;
        int row = row0 + r;
        if (row < n) {
            g_als1[row * 4 + hh] = s_als[r][hh];
            g_ald1[row * 4 + hh] = s_ald[r][hh];
        }
    }
}

// ---------------- k3: layer-1 softmax denominators --------------------------
__global__ void k_passA1(int ET) {
    int i = blockIdx.x * blockDim.x + threadIdx.x;
    if (i >= ET) return;
    int s = g_src[i], d = g_dst[i];
    const float4 as = *(const float4*)&g_als1[s * 4];
    const float4 ad = *(const float4*)&g_ald1[d * 4];
    float4 ex;
    ex.x = lexp(as.x + ad.x);
    ex.y = lexp(as.y + ad.y);
    ex.z = lexp(as.z + ad.z);
    ex.w = lexp(as.w + ad.w);
    red_add_v4(&g_den1[d * 4], ex);
}

// ---------------- k4: layer-1 aggregate (warp per edge, v4 atomics) ---------
__global__ void k_passB1(int ET) {
    int warp = (blockIdx.x * blockDim.x + threadIdx.x) >> 5;
    int lane = threadIdx.x & 31;
    if (warp >= ET) return;
    int s = g_src[warp], d = g_dst[warp];
    int h = lane >> 3;                               // head for cols 4*lane..
    float e  = g_als1[s * 4 + h] + g_ald1[d * 4 + h];
    float alpha = __fdividef(lexp(e), g_den1[d * 4 + h]);
    float4 hv = *(const float4*)&g_h1[(size_t)s * 128 + lane * 4];
    float4 m  = make_float4(hv.x * alpha, hv.y * alpha, hv.z * alpha, hv.w * alpha);
    red_add_v4(&g_agg1[(size_t)d * 128 + lane * 4], m);
}

// ---------------- k5: relu(agg1+b1) @ W2 + layer-2 logits -------------------
// 128 threads, 8 nodes/block, 16 threads per node (one per output channel).
__global__ void __launch_bounds__(128)
k_layer2(const float* __restrict__ b1, const float* __restrict__ W2,
         const float* __restrict__ a_src2, const float* __restrict__ a_dst2,
         int n) {
    __shared__ float W2s[128 * 16];
    __shared__ float b1s[128];
    __shared__ float xs[8][128];
    __shared__ float outs[8][16];
    __shared__ float sa2[16], sd2[16];

    int t = threadIdx.x;
    int row0 = blockIdx.x * 8;

    for (int i = t; i < 128 * 16 / 4; i += 128)
        ((float4*)W2s)[i] = ((const float4*)W2)[i];
    b1s[t] = b1[t];
    if (t < 16) { sa2[t] = a_src2[t]; sd2[t] = a_dst2[t]; }
    __syncthreads();

    int nl = t >> 4, seg = t & 15;
    int row = row0 + nl;
    {
        int c = seg * 8;
#pragma unroll
        for (int j = 0; j < 2; j++) {
            float4 v = (row < n)
                ? *(const float4*)&g_agg1[(size_t)row * 128 + c + 4 * j]
                : make_float4(0.f, 0.f, 0.f, 0.f);
            v.x = fmaxf(v.x + b1s[c + 4 * j + 0], 0.f);
            v.y = fmaxf(v.y + b1s[c + 4 * j + 1], 0.f);
            v.z = fmaxf(v.z + b1s[c + 4 * j + 2], 0.f);
            v.w = fmaxf(v.w + b1s[c + 4 * j + 3], 0.f);
            *(float4*)&xs[nl][c + 4 * j] = v;
        }
    }
    __syncthreads();

    int o = seg;
    float acc = 0.f;
#pragma unroll 8
    for (int k = 0; k < 128; k += 4) {
        float4 xv = *(const float4*)&xs[nl][k];
        acc += xv.x * W2s[(k + 0) * 16 + o] + xv.y * W2s[(k + 1) * 16 + o]
             + xv.z * W2s[(k + 2) * 16 + o] + xv.w * W2s[(k + 3) * 16 + o];
    }
    outs[nl][o] = acc;
    if (row < n) g_h2[row * 16 + o] = acc;
    __syncthreads();

    if (o == 0 && row < n) {
        float ss = 0.f, sd = 0.f;
#pragma unroll
        for (int j = 0; j < 16; j++) {
            ss += outs[nl][j] * sa2[j];
            sd += outs[nl][j] * sd2[j];
        }
        g_als2[row] = ss;
        g_ald2[row] = sd;
    }
}

// ---------------- k6: layer-2 denominators ----------------------------------
__global__ void k_passA2(int ET) {
    int i = blockIdx.x * blockDim.x + threadIdx.x;
    if (i >= ET) return;
    int s = g_src[i], d = g_dst[i];
    float ex = lexp(g_als2[s] + g_ald2[d]);
    red_add_f(&g_den2[d], ex);
}

// ---------------- k7: layer-2 aggregate into d_out --------------------------
// 4 threads per edge, each owns one float4 of the 16-channel message.
__global__ void k_passB2(float* __restrict__ out, int ET) {
    int g = blockIdx.x * blockDim.x + threadIdx.x;
    int e = g >> 2, q = g & 3;
    if (e >= ET) return;
    int s = g_src[e], d = g_dst[e];
    float ev = g_als2[s] + g_ald2[d];
    float alpha = __fdividef(lexp(ev), g_den2[d]);
    float4 hv = *(const float4*)&g_h2[s * 16 + q * 4];
    float4 m  = make_float4(hv.x * alpha, hv.y * alpha, hv.z * alpha, hv.w * alpha);
    red_add_v4(&out[d * 16 + q * 4], m);
}

// ---------------- k8: + b2 ---------------------------------------------------
__global__ void k_addb2(float* __restrict__ out, const float* __restrict__ b2, int N) {
    int i = blockIdx.x * blockDim.x + threadIdx.x;
    if (i < N * 16) out[i] += __ldg(&b2[i & 15]);
}

// ---------------- launch -----------------------------------------------------
extern "C" void kernel_launch(void* const* d_in, const int* in_sizes, int n_in,
                              void* d_out, int out_size) {
    const float* x      = (const float*)d_in[0];
    const int*   ei     = (const int*)d_in[1];     // JAX x64 off -> int32
    const float* W1     = (const float*)d_in[2];
    const float* a_src1 = (const float*)d_in[3];
    const float* a_dst1 = (const float*)d_in[4];
    const float* b1     = (const float*)d_in[5];
    const float* W2     = (const float*)d_in[6];
    const float* a_src2 = (const float*)d_in[7];
    const float* a_dst2 = (const float*)d_in[8];
    const float* b2     = (const float*)d_in[9];
    float* out = (float*)d_out;

    int N  = in_sizes[0] / 128;
    int E  = in_sizes[1] / 2;
    int ET = E + N;

    k_prep<<<(ET + 255) / 256, 256>>>(ei, E, ET);
    k_init<<<(N * 128 + 255) / 256, 256>>>(out, N);

    static int smem_set = 0;
    if (!smem_set) {
        cudaFuncSetAttribute(k_gemm1, cudaFuncAttributeMaxDynamicSharedMemorySize,
                             (128 * 128 + G1_ROWS * 128) * sizeof(float));
        smem_set = 1;
    }
    k_gemm1<<<(N + G1_ROWS - 1) / G1_ROWS, 256,
              (128 * 128 + G1_ROWS * 128) * sizeof(float)>>>(x, W1, a_src1, a_dst1, N);

    k_passA1<<<(ET + 255) / 256, 256>>>(ET);
    k_passB1<<<(ET + 7) / 8, 256>>>(ET);
    k_layer2<<<(N + 7) / 8, 128>>>(b1, W2, a_src2, a_dst2, N);
    k_passA2<<<(ET + 255) / 256, 256>>>(ET);
    k_passB2<<<(ET * 4 + 255) / 256, 256>>>(out, ET);
    k_addb2<<<(N * 16 + 255) / 256, 256>>>(out, b2, N);
}

// round 4
// speedup vs baseline: 1.5403x; 1.5403x over previous
#include <cuda_runtime.h>

#define NEG 0.2f
#define MAXN 100000
#define MAXE 1600000
#define MAXET (MAXN + MAXE)
#define SCAN_B 256
#define MAXBLK 512   // >= ceil(MAXN/SCAN_B) = 391

// ---------------- scratch ----------------------------------------------------
__device__ int   g_src[MAXET];
__device__ int   g_dst[MAXET];
__device__ int   g_csrc[MAXET];           // CSR column (src) indices
__device__ int   g_deg[MAXN];
__device__ int   g_tmp[MAXN];             // block-local exclusive scan
__device__ int   g_bsum[MAXBLK];
__device__ int   g_boff[MAXBLK];
__device__ int   g_rowptr[MAXN + 1];
__device__ int   g_wp[MAXN];              // scatter write pointers
__device__ float g_h1 [(size_t)MAXN * 128];
__device__ float g_x2 [(size_t)MAXN * 128];   // relu(agg1+b1): layer-2 input
__device__ float g_als1[MAXN * 4];
__device__ float g_ald1[MAXN * 4];
__device__ float g_h2  [MAXN * 16];
__device__ float g_als2[MAXN];
__device__ float g_ald2[MAXN];

// ---------------- helpers ----------------------------------------------------
__device__ __forceinline__ float lexp(float e) {
    e = e > 0.f ? e : NEG * e;            // LeakyReLU(0.2)
    return __expf(e);                     // softmax shift-invariant: no max pass
}

// ---------------- k_init: zero degree histogram ------------------------------
__global__ void k_init(int N) {
    int i = blockIdx.x * blockDim.x + threadIdx.x;
    if (i < N) g_deg[i] = 0;
}

// ---------------- k_prep: edges->int32 scratch + self loops + histogram ------
__global__ void k_prep(const int* __restrict__ ei, int E, int ET) {
    int i = blockIdx.x * blockDim.x + threadIdx.x;
    if (i >= ET) return;
    int s, d;
    if (i < E) { s = ei[i]; d = ei[E + i]; }
    else       { s = d = i - E; }
    g_src[i] = s;
    g_dst[i] = d;
    atomicAdd(&g_deg[d], 1);
}

// ---------------- scan (3-kernel exclusive prefix sum over deg) --------------
__global__ void k_scan1(int N) {
    __shared__ int sm[SCAN_B];
    int i = blockIdx.x * SCAN_B + threadIdx.x;
    int v = (i < N) ? g_deg[i] : 0;
    sm[threadIdx.x] = v;
    __syncthreads();
    for (int o = 1; o < SCAN_B; o <<= 1) {
        int t = (threadIdx.x >= o) ? sm[threadIdx.x - o] : 0;
        __syncthreads();
        sm[threadIdx.x] += t;
        __syncthreads();
    }
    if (i < N) g_tmp[i] = sm[threadIdx.x] - v;      // exclusive
    if (threadIdx.x == SCAN_B - 1) g_bsum[blockIdx.x] = sm[SCAN_B - 1];
}

__global__ void k_scan2(int nb) {
    __shared__ int sm[MAXBLK];
    int t = threadIdx.x;
    int v = (t < nb) ? g_bsum[t] : 0;
    sm[t] = v;
    __syncthreads();
    for (int o = 1; o < MAXBLK; o <<= 1) {
        int u = (t >= o) ? sm[t - o] : 0;
        __syncthreads();
        sm[t] += u;
        __syncthreads();
    }
    if (t < nb) g_boff[t] = sm[t] - v;              // exclusive
}

__global__ void k_scan3(int N, int ET) {
    int i = blockIdx.x * blockDim.x + threadIdx.x;
    if (i < N) {
        int r = g_tmp[i] + g_boff[i >> 8];
        g_rowptr[i] = r;
        g_wp[i] = r;
    }
    if (i == 0) g_rowptr[N] = ET;
}

// ---------------- k_scatter: build CSR ---------------------------------------
__global__ void k_scatter(int ET) {
    int i = blockIdx.x * blockDim.x + threadIdx.x;
    if (i >= ET) return;
    int d = g_dst[i];
    int pos = atomicAdd(&g_wp[d], 1);
    g_csrc[pos] = g_src[i];
}

// ---------------- k_gemm1: x@W1 + attention logits, fused --------------------
#define G1_ROWS 64
__global__ void __launch_bounds__(256)
k_gemm1(const float* __restrict__ x, const float* __restrict__ W1,
        const float* __restrict__ a_src1, const float* __restrict__ a_dst1,
        int n) {
    extern __shared__ float sm[];
    float* Ws = sm;                                      // [128][128]
    float (*xs)[128] = (float(*)[128])(sm + 128 * 128);  // [64][128]
    __shared__ float s_as[128], s_ad[128];
    __shared__ float s_als[G1_ROWS][4], s_ald[G1_ROWS][4];

    int t = threadIdx.x;
    int row0 = blockIdx.x * G1_ROWS;

    for (int i = t; i < 128 * 128 / 4; i += 256)
        ((float4*)Ws)[i] = ((const float4*)W1)[i];
    if (t < 128) { s_as[t] = a_src1[t]; s_ad[t] = a_dst1[t]; }
    if (t < G1_ROWS * 4) { ((float*)s_als)[t] = 0.f; ((float*)s_ald)[t] = 0.f; }
    for (int i = t; i < G1_ROWS * 32; i += 256) {
        int r = i >> 5, kq = i & 31;
        int row = row0 + r;
        float4 v = (row < n) ? ((const float4*)x)[(size_t)row * 32 + kq]
                             : make_float4(0.f, 0.f, 0.f, 0.f);
        ((float4*)xs[r])[kq] = v;
    }
    __syncthreads();

    const int c0 = (t & 31) * 4;
    const int r0 = (t >> 5) * 8;
    float acc[8][4];
#pragma unroll
    for (int r = 0; r < 8; r++)
#pragma unroll
        for (int c = 0; c < 4; c++) acc[r][c] = 0.f;

#pragma unroll 4
    for (int k = 0; k < 128; k += 4) {
        float4 w0 = *(const float4*)&Ws[(k + 0) * 128 + c0];
        float4 w1 = *(const float4*)&Ws[(k + 1) * 128 + c0];
        float4 w2 = *(const float4*)&Ws[(k + 2) * 128 + c0];
        float4 w3 = *(const float4*)&Ws[(k + 3) * 128 + c0];
#pragma unroll
        for (int r = 0; r < 8; r++) {
            float4 xv = *(const float4*)&xs[r0 + r][k];
            acc[r][0] += xv.x * w0.x + xv.y * w1.x + xv.z * w2.x + xv.w * w3.x;
            acc[r][1] += xv.x * w0.y + xv.y * w1.y + xv.z * w2.y + xv.w * w3.y;
            acc[r][2] += xv.x * w0.z + xv.y * w1.z + xv.z * w2.z + xv.w * w3.z;
            acc[r][3] += xv.x * w0.w + xv.y * w1.w + xv.z * w2.w + xv.w * w3.w;
        }
    }

    const int head = c0 >> 5;
#pragma unroll
    for (int r = 0; r < 8; r++) {
        int row = row0 + r0 + r;
        if (row < n) {
            *(float4*)&g_h1[(size_t)row * 128 + c0] =
                make_float4(acc[r][0], acc[r][1], acc[r][2], acc[r][3]);
            float ps = acc[r][0] * s_as[c0]     + acc[r][1] * s_as[c0 + 1]
                     + acc[r][2] * s_as[c0 + 2] + acc[r][3] * s_as[c0 + 3];
            float pd = acc[r][0] * s_ad[c0]     + acc[r][1] * s_ad[c0 + 1]
                     + acc[r][2] * s_ad[c0 + 2] + acc[r][3] * s_ad[c0 + 3];
            atomicAdd(&s_als[r0 + r][head], ps);
            atomicAdd(&s_ald[r0 + r][head], pd);
        }
    }
    __syncthreads();
    if (t < G1_ROWS * 4) {
        int r = t >> 2, hh = t & 3;
        int row = row0 + r;
        if (row < n) {
            g_als1[row * 4 + hh] = s_als[r][hh];
            g_ald1[row * 4 + hh] = s_ald[r][hh];
        }
    }
}

// ---------------- k_agg1: CSR warp-per-node aggregate (no atomics) -----------
// out: g_x2[d] = relu( (sum_e exp*h1[s]) / (sum_e exp) + b1 )
__global__ void __launch_bounds__(256)
k_agg1(const float* __restrict__ b1, int N) {
    int node = (blockIdx.x * blockDim.x + threadIdx.x) >> 5;
    if (node >= N) return;
    int lane = threadIdx.x & 31;
    int h = lane >> 3;
    float ald = __ldg(&g_ald1[node * 4 + h]);
    int j   = g_rowptr[node];
    int end = g_rowptr[node + 1];
    float4 acc = make_float4(0.f, 0.f, 0.f, 0.f);
    float den = 0.f;

    for (; j + 1 < end; j += 2) {
        int s0 = __ldg(&g_csrc[j]);
        int s1 = __ldg(&g_csrc[j + 1]);
        float w0 = lexp(__ldg(&g_als1[s0 * 4 + h]) + ald);
        float w1 = lexp(__ldg(&g_als1[s1 * 4 + h]) + ald);
        float4 v0 = *(const float4*)&g_h1[(size_t)s0 * 128 + lane * 4];
        float4 v1 = *(const float4*)&g_h1[(size_t)s1 * 128 + lane * 4];
        acc.x += w0 * v0.x + w1 * v1.x;
        acc.y += w0 * v0.y + w1 * v1.y;
        acc.z += w0 * v0.z + w1 * v1.z;
        acc.w += w0 * v0.w + w1 * v1.w;
        den   += w0 + w1;
    }
    if (j < end) {
        int s0 = __ldg(&g_csrc[j]);
        float w0 = lexp(__ldg(&g_als1[s0 * 4 + h]) + ald);
        float4 v0 = *(const float4*)&g_h1[(size_t)s0 * 128 + lane * 4];
        acc.x += w0 * v0.x; acc.y += w0 * v0.y;
        acc.z += w0 * v0.z; acc.w += w0 * v0.w;
        den += w0;
    }

    float inv = __fdividef(1.f, den);
    float4 bb = *(const float4*)&b1[lane * 4];
    float4 o;
    o.x = fmaxf(acc.x * inv + bb.x, 0.f);
    o.y = fmaxf(acc.y * inv + bb.y, 0.f);
    o.z = fmaxf(acc.z * inv + bb.z, 0.f);
    o.w = fmaxf(acc.w * inv + bb.w, 0.f);
    *(float4*)&g_x2[(size_t)node * 128 + lane * 4] = o;
}

// ---------------- k_layer2: x2 @ W2 + layer-2 logits -------------------------
__global__ void __launch_bounds__(128)
k_layer2(const float* __restrict__ W2,
         const float* __restrict__ a_src2, const float* __restrict__ a_dst2,
         int n) {
    __shared__ float W2s[128 * 16];
    __shared__ float xs[8][128];
    __shared__ float outs[8][16];
    __shared__ float sa2[16], sd2[16];

    int t = threadIdx.x;
    int row0 = blockIdx.x * 8;

    for (int i = t; i < 128 * 16 / 4; i += 128)
        ((float4*)W2s)[i] = ((const float4*)W2)[i];
    if (t < 16) { sa2[t] = a_src2[t]; sd2[t] = a_dst2[t]; }
    __syncthreads();

    int nl = t >> 4, seg = t & 15;
    int row = row0 + nl;
    {
        int c = seg * 8;
#pragma unroll
        for (int jj = 0; jj < 2; jj++) {
            float4 v = (row < n)
                ? *(const float4*)&g_x2[(size_t)row * 128 + c + 4 * jj]
                : make_float4(0.f, 0.f, 0.f, 0.f);
            *(float4*)&xs[nl][c + 4 * jj] = v;
        }
    }
    __syncthreads();

    int o = seg;
    float acc = 0.f;
#pragma unroll 8
    for (int k = 0; k < 128; k += 4) {
        float4 xv = *(const float4*)&xs[nl][k];
        acc += xv.x * W2s[(k + 0) * 16 + o] + xv.y * W2s[(k + 1) * 16 + o]
             + xv.z * W2s[(k + 2) * 16 + o] + xv.w * W2s[(k + 3) * 16 + o];
    }
    outs[nl][o] = acc;
    if (row < n) g_h2[row * 16 + o] = acc;
    __syncthreads();

    if (o == 0 && row < n) {
        float ss = 0.f, sd = 0.f;
#pragma unroll
        for (int jj = 0; jj < 16; jj++) {
            ss += outs[nl][jj] * sa2[jj];
            sd += outs[nl][jj] * sd2[jj];
        }
        g_als2[row] = ss;
        g_ald2[row] = sd;
    }
}

// ---------------- k_agg2: CSR 16-thread-per-node aggregate into d_out --------
__global__ void __launch_bounds__(256)
k_agg2(float* __restrict__ out, const float* __restrict__ b2, int N) {
    int g = blockIdx.x * blockDim.x + threadIdx.x;
    int node = g >> 4;
    if (node >= N) return;
    int c = g & 15;
    float ald = __ldg(&g_ald2[node]);
    int j   = g_rowptr[node];
    int end = g_rowptr[node + 1];
    float acc = 0.f, den = 0.f;

    for (; j + 1 < end; j += 2) {
        int s0 = __ldg(&g_csrc[j]);
        int s1 = __ldg(&g_csrc[j + 1]);
        float w0 = lexp(__ldg(&g_als2[s0]) + ald);
        float w1 = lexp(__ldg(&g_als2[s1]) + ald);
        float h0 = __ldg(&g_h2[s0 * 16 + c]);
        float h1v = __ldg(&g_h2[s1 * 16 + c]);
        acc += w0 * h0 + w1 * h1v;
        den += w0 + w1;
    }
    if (j < end) {
        int s0 = __ldg(&g_csrc[j]);
        float w0 = lexp(__ldg(&g_als2[s0]) + ald);
        acc += w0 * __ldg(&g_h2[s0 * 16 + c]);
        den += w0;
    }

    out[node * 16 + c] = acc * __fdividef(1.f, den) + __ldg(&b2[c]);
}

// ---------------- launch ------------------------------------------------------
extern "C" void kernel_launch(void* const* d_in, const int* in_sizes, int n_in,
                              void* d_out, int out_size) {
    const float* x      = (const float*)d_in[0];
    const int*   ei     = (const int*)d_in[1];     // JAX x64 off -> int32
    const float* W1     = (const float*)d_in[2];
    const float* a_src1 = (const float*)d_in[3];
    const float* a_dst1 = (const float*)d_in[4];
    const float* b1     = (const float*)d_in[5];
    const float* W2     = (const float*)d_in[6];
    const float* a_src2 = (const float*)d_in[7];
    const float* a_dst2 = (const float*)d_in[8];
    const float* b2     = (const float*)d_in[9];
    float* out = (float*)d_out;

    int N  = in_sizes[0] / 128;
    int E  = in_sizes[1] / 2;
    int ET = E + N;
    int nb = (N + SCAN_B - 1) / SCAN_B;

    k_init<<<(N + 255) / 256, 256>>>(N);
    k_prep<<<(ET + 255) / 256, 256>>>(ei, E, ET);
    k_scan1<<<nb, SCAN_B>>>(N);
    k_scan2<<<1, MAXBLK>>>(nb);
    k_scan3<<<(N + 255) / 256, 256>>>(N, ET);
    k_scatter<<<(ET + 255) / 256, 256>>>(ET);

    static int smem_set = 0;
    if (!smem_set) {
        cudaFuncSetAttribute(k_gemm1, cudaFuncAttributeMaxDynamicSharedMemorySize,
                             (128 * 128 + G1_ROWS * 128) * sizeof(float));
        smem_set = 1;
    }
    k_gemm1<<<(N + G1_ROWS - 1) / G1_ROWS, 256,
              (128 * 128 + G1_ROWS * 128) * sizeof(float)>>>(x, W1, a_src1, a_dst1, N);

    k_agg1<<<(N * 32 + 255) / 256, 256>>>(b1, N);
    k_layer2<<<(N + 7) / 8, 128>>>(W2, a_src2, a_dst2, N);
    k_agg2<<<(N * 16 + 255) / 256, 256>>>(out, b2, N);
}

// round 6
// speedup vs baseline: 1.6514x; 1.0721x over previous
#include <cuda_runtime.h>
#include <cuda_fp16.h>

#define NEG 0.2f
#define MAXN 100000
#define MAXE 1600000
#define MAXET (MAXN + MAXE)

// ---------------- scratch ----------------------------------------------------
__device__ int     g_csrc[MAXET];              // CSR column (src) indices
__device__ int     g_deg[MAXN];
__device__ int     g_rowptr[MAXN];
__device__ int     g_wp[MAXN];
__device__ int     g_total;
__device__ __half2 g_h1h[(size_t)MAXN * 64];   // h1 as fp16 (gather payload)
__device__ float   g_x2 [(size_t)MAXN * 128];  // relu(agg1+b1): layer-2 input
__device__ float   g_als1[MAXN * 4];
__device__ float   g_ald1[MAXN * 4];
__device__ __half2 g_h2h[MAXN * 8];            // h2 as fp16
__device__ float   g_als2[MAXN];
__device__ float   g_ald2[MAXN];

// ---------------- helpers ----------------------------------------------------
__device__ __forceinline__ float lexp(float e) {
    e = e > 0.f ? e : NEG * e;            // LeakyReLU(0.2)
    return __expf(e);                     // softmax shift-invariant: no max pass
}

// ---------------- k_zero ------------------------------------------------------
__global__ void k_zero(int N) {
    int i = blockIdx.x * blockDim.x + threadIdx.x;
    if (i < N) g_deg[i] = 0;
    if (i == 0) g_total = 0;
}

// ---------------- k_hist: degree histogram (incl. self loops) ----------------
__global__ void k_hist(const int* __restrict__ ei, int E, int ET) {
    int i = blockIdx.x * blockDim.x + threadIdx.x;
    if (i >= ET) return;
    int d = (i < E) ? ei[E + i] : (i - E);
    atomicAdd(&g_deg[d], 1);
}

// ---------------- k_offsets: segment offsets via atomic bump -----------------
// Segment order is arbitrary; aggregation is order-independent per node.
__global__ void k_offsets(int N) {
    int i = blockIdx.x * blockDim.x + threadIdx.x;
    if (i >= N) return;
    int d = g_deg[i];
    int off = atomicAdd(&g_total, d);
    g_rowptr[i] = off;
    g_wp[i] = off;
}

// ---------------- k_scatter: build CSR from ei --------------------------------
__global__ void k_scatter(const int* __restrict__ ei, int E, int ET) {
    int i = blockIdx.x * blockDim.x + threadIdx.x;
    if (i >= ET) return;
    int s, d;
    if (i < E) { s = ei[i]; d = ei[E + i]; }
    else       { s = d = i - E; }
    int pos = atomicAdd(&g_wp[d], 1);
    g_csrc[pos] = s;
}

// ---------------- k_gemm1: x@W1 + attention logits, fused --------------------
#define G1_ROWS 64
__global__ void __launch_bounds__(256)
k_gemm1(const float* __restrict__ x, const float* __restrict__ W1,
        const float* __restrict__ a_src1, const float* __restrict__ a_dst1,
        int n) {
    extern __shared__ float sm[];
    float* Ws = sm;                                      // [128][128]
    float (*xs)[128] = (float(*)[128])(sm + 128 * 128);  // [64][128]
    __shared__ float s_as[128], s_ad[128];
    __shared__ float s_als[G1_ROWS][4], s_ald[G1_ROWS][4];

    int t = threadIdx.x;
    int row0 = blockIdx.x * G1_ROWS;

    for (int i = t; i < 128 * 128 / 4; i += 256)
        ((float4*)Ws)[i] = ((const float4*)W1)[i];
    if (t < 128) { s_as[t] = a_src1[t]; s_ad[t] = a_dst1[t]; }
    if (t < G1_ROWS * 4) { ((float*)s_als)[t] = 0.f; ((float*)s_ald)[t] = 0.f; }
    for (int i = t; i < G1_ROWS * 32; i += 256) {
        int r = i >> 5, kq = i & 31;
        int row = row0 + r;
        float4 v = (row < n) ? ((const float4*)x)[(size_t)row * 32 + kq]
                             : make_float4(0.f, 0.f, 0.f, 0.f);
        ((float4*)xs[r])[kq] = v;
    }
    __syncthreads();

    const int c0 = (t & 31) * 4;
    const int r0 = (t >> 5) * 8;
    float acc[8][4];
#pragma unroll
    for (int r = 0; r < 8; r++)
#pragma unroll
        for (int c = 0; c < 4; c++) acc[r][c] = 0.f;

#pragma unroll 4
    for (int k = 0; k < 128; k += 4) {
        float4 w0 = *(const float4*)&Ws[(k + 0) * 128 + c0];
        float4 w1 = *(const float4*)&Ws[(k + 1) * 128 + c0];
        float4 w2 = *(const float4*)&Ws[(k + 2) * 128 + c0];
        float4 w3 = *(const float4*)&Ws[(k + 3) * 128 + c0];
#pragma unroll
        for (int r = 0; r < 8; r++) {
            float4 xv = *(const float4*)&xs[r0 + r][k];
            acc[r][0] += xv.x * w0.x + xv.y * w1.x + xv.z * w2.x + xv.w * w3.x;
            acc[r][1] += xv.x * w0.y + xv.y * w1.y + xv.z * w2.y + xv.w * w3.y;
            acc[r][2] += xv.x * w0.z + xv.y * w1.z + xv.z * w2.z + xv.w * w3.z;
            acc[r][3] += xv.x * w0.w + xv.y * w1.w + xv.z * w2.w + xv.w * w3.w;
        }
    }

    const int head = c0 >> 5;
#pragma unroll
    for (int r = 0; r < 8; r++) {
        int row = row0 + r0 + r;
        if (row < n) {
            __half2 p0 = __floats2half2_rn(acc[r][0], acc[r][1]);
            __half2 p1 = __floats2half2_rn(acc[r][2], acc[r][3]);
            uint2 pk;
            pk.x = *(unsigned int*)&p0;
            pk.y = *(unsigned int*)&p1;
            *(uint2*)&g_h1h[(size_t)row * 64 + (c0 >> 1)] = pk;
            float ps = acc[r][0] * s_as[c0]     + acc[r][1] * s_as[c0 + 1]
                     + acc[r][2] * s_as[c0 + 2] + acc[r][3] * s_as[c0 + 3];
            float pd = acc[r][0] * s_ad[c0]     + acc[r][1] * s_ad[c0 + 1]
                     + acc[r][2] * s_ad[c0 + 2] + acc[r][3] * s_ad[c0 + 3];
            atomicAdd(&s_als[r0 + r][head], ps);
            atomicAdd(&s_ald[r0 + r][head], pd);
        }
    }
    __syncthreads();
    if (t < G1_ROWS * 4) {
        int r = t >> 2, hh = t & 3;
        int row = row0 + r;
        if (row < n) {
            g_als1[row * 4 + hh] = s_als[r][hh];
            g_ald1[row * 4 + hh] = s_ald[r][hh];
        }
    }
}

// ---------------- k_agg1: CSR warp-per-node aggregate (no atomics) -----------
__global__ void __launch_bounds__(256)
k_agg1(const float* __restrict__ b1, int N) {
    int node = (blockIdx.x * blockDim.x + threadIdx.x) >> 5;
    if (node >= N) return;
    int lane = threadIdx.x & 31;
    int h = lane >> 3;
    float ald = __ldg(&g_ald1[node * 4 + h]);
    int j   = g_rowptr[node];
    int end = j + g_deg[node];
    float4 acc = make_float4(0.f, 0.f, 0.f, 0.f);
    float den = 0.f;

    for (; j + 1 < end; j += 2) {
        int s0 = __ldg(&g_csrc[j]);
        int s1 = __ldg(&g_csrc[j + 1]);
        float w0 = lexp(__ldg(&g_als1[s0 * 4 + h]) + ald);
        float w1 = lexp(__ldg(&g_als1[s1 * 4 + h]) + ald);
        uint2 u0 = *(const uint2*)&g_h1h[(size_t)s0 * 64 + lane * 2];
        uint2 u1 = *(const uint2*)&g_h1h[(size_t)s1 * 64 + lane * 2];
        float2 a0 = __half22float2(*(__half2*)&u0.x);
        float2 a1 = __half22float2(*(__half2*)&u0.y);
        float2 c0 = __half22float2(*(__half2*)&u1.x);
        float2 c1 = __half22float2(*(__half2*)&u1.y);
        acc.x += w0 * a0.x + w1 * c0.x;
        acc.y += w0 * a0.y + w1 * c0.y;
        acc.z += w0 * a1.x + w1 * c1.x;
        acc.w += w0 * a1.y + w1 * c1.y;
        den   += w0 + w1;
    }
    if (j < end) {
        int s0 = __ldg(&g_csrc[j]);
        float w0 = lexp(__ldg(&g_als1[s0 * 4 + h]) + ald);
        uint2 u0 = *(const uint2*)&g_h1h[(size_t)s0 * 64 + lane * 2];
        float2 a0 = __half22float2(*(__half2*)&u0.x);
        float2 a1 = __half22float2(*(__half2*)&u0.y);
        acc.x += w0 * a0.x; acc.y += w0 * a0.y;
        acc.z += w0 * a1.x; acc.w += w0 * a1.y;
        den += w0;
    }

    float inv = __fdividef(1.f, den);
    float4 bb = *(const float4*)&b1[lane * 4];
    float4 o;
    o.x = fmaxf(acc.x * inv + bb.x, 0.f);
    o.y = fmaxf(acc.y * inv + bb.y, 0.f);
    o.z = fmaxf(acc.z * inv + bb.z, 0.f);
    o.w = fmaxf(acc.w * inv + bb.w, 0.f);
    *(float4*)&g_x2[(size_t)node * 128 + lane * 4] = o;
}

// ---------------- k_layer2: x2 @ W2 + layer-2 logits -------------------------
__global__ void __launch_bounds__(128)
k_layer2(const float* __restrict__ W2,
         const float* __restrict__ a_src2, const float* __restrict__ a_dst2,
         int n) {
    __shared__ float W2s[128 * 16];
    __shared__ float xs[8][128];
    __shared__ float outs[8][16];
    __shared__ float sa2[16], sd2[16];

    int t = threadIdx.x;
    int row0 = blockIdx.x * 8;

    for (int i = t; i < 128 * 16 / 4; i += 128)
        ((float4*)W2s)[i] = ((const float4*)W2)[i];
    if (t < 16) { sa2[t] = a_src2[t]; sd2[t] = a_dst2[t]; }
    __syncthreads();

    int nl = t >> 4, seg = t & 15;
    int row = row0 + nl;
    {
        int c = seg * 8;
#pragma unroll
        for (int jj = 0; jj < 2; jj++) {
            float4 v = (row < n)
                ? *(const float4*)&g_x2[(size_t)row * 128 + c + 4 * jj]
                : make_float4(0.f, 0.f, 0.f, 0.f);
            *(float4*)&xs[nl][c + 4 * jj] = v;
        }
    }
    __syncthreads();

    int o = seg;
    float acc = 0.f;
#pragma unroll 8
    for (int k = 0; k < 128; k += 4) {
        float4 xv = *(const float4*)&xs[nl][k];
        acc += xv.x * W2s[(k + 0) * 16 + o] + xv.y * W2s[(k + 1) * 16 + o]
             + xv.z * W2s[(k + 2) * 16 + o] + xv.w * W2s[(k + 3) * 16 + o];
    }
    outs[nl][o] = acc;
    // pack channel pair (o even) -> fp16x2 via shfl from o+1 (same node, same warp)
    float accn = __shfl_down_sync(0xffffffffu, acc, 1);
    if (!(o & 1) && row < n)
        g_h2h[row * 8 + (o >> 1)] = __floats2half2_rn(acc, accn);
    __syncthreads();

    if (o == 0 && row < n) {
        float ss = 0.f, sd = 0.f;
#pragma unroll
        for (int jj = 0; jj < 16; jj++) {
            ss += outs[nl][jj] * sa2[jj];
            sd += outs[nl][jj] * sd2[jj];
        }
        g_als2[row] = ss;
        g_ald2[row] = sd;
    }
}

// ---------------- k_agg2: CSR 8-thread-per-node aggregate into d_out ---------
__global__ void __launch_bounds__(256)
k_agg2(float* __restrict__ out, const float* __restrict__ b2, int N) {
    int g = blockIdx.x * blockDim.x + threadIdx.x;
    int node = g >> 3;
    if (node >= N) return;
    int c = g & 7;                         // channel pair index
    float ald = __ldg(&g_ald2[node]);
    int j   = g_rowptr[node];
    int end = j + g_deg[node];
    float ax = 0.f, ay = 0.f, den = 0.f;

    for (; j + 1 < end; j += 2) {
        int s0 = __ldg(&g_csrc[j]);
        int s1 = __ldg(&g_csrc[j + 1]);
        float w0 = lexp(__ldg(&g_als2[s0]) + ald);
        float w1 = lexp(__ldg(&g_als2[s1]) + ald);
        float2 f0 = __half22float2(g_h2h[s0 * 8 + c]);
        float2 f1 = __half22float2(g_h2h[s1 * 8 + c]);
        ax += w0 * f0.x + w1 * f1.x;
        ay += w0 * f0.y + w1 * f1.y;
        den += w0 + w1;
    }
    if (j < end) {
        int s0 = __ldg(&g_csrc[j]);
        float w0 = lexp(__ldg(&g_als2[s0]) + ald);
        float2 f0 = __half22float2(g_h2h[s0 * 8 + c]);
        ax += w0 * f0.x;
        ay += w0 * f0.y;
        den += w0;
    }

    float inv = __fdividef(1.f, den);
    float2 ov;
    ov.x = ax * inv + __ldg(&b2[2 * c]);
    ov.y = ay * inv + __ldg(&b2[2 * c + 1]);
    *(float2*)&out[node * 16 + 2 * c] = ov;
}

// ---------------- launch ------------------------------------------------------
extern "C" void kernel_launch(void* const* d_in, const int* in_sizes, int n_in,
                              void* d_out, int out_size) {
    const float* x      = (const float*)d_in[0];
    const int*   ei     = (const int*)d_in[1];     // JAX x64 off -> int32
    const float* W1     = (const float*)d_in[2];
    const float* a_src1 = (const float*)d_in[3];
    const float* a_dst1 = (const float*)d_in[4];
    const float* b1     = (const float*)d_in[5];
    const float* W2     = (const float*)d_in[6];
    const float* a_src2 = (const float*)d_in[7];
    const float* a_dst2 = (const float*)d_in[8];
    const float* b2     = (const float*)d_in[9];
    float* out = (float*)d_out;

    int N  = in_sizes[0] / 128;
    int E  = in_sizes[1] / 2;
    int ET = E + N;

    k_zero<<<(N + 255) / 256, 256>>>(N);
    k_hist<<<(ET + 255) / 256, 256>>>(ei, E, ET);
    k_offsets<<<(N + 255) / 256, 256>>>(N);
    k_scatter<<<(ET + 255) / 256, 256>>>(ei, E, ET);

    static int smem_set = 0;
    if (!smem_set) {
        cudaFuncSetAttribute(k_gemm1, cudaFuncAttributeMaxDynamicSharedMemorySize,
                             (128 * 128 + G1_ROWS * 128) * sizeof(float));
        smem_set = 1;
    }
    k_gemm1<<<(N + G1_ROWS - 1) / G1_ROWS, 256,
              (128 * 128 + G1_ROWS * 128) * sizeof(float)>>>(x, W1, a_src1, a_dst1, N);

    k_agg1<<<(N * 32 + 255) / 256, 256>>>(b1, N);
    k_layer2<<<(N + 7) / 8, 128>>>(W2, a_src2, a_dst2, N);
    k_agg2<<<(N * 8 + 255) / 256, 256>>>(out, b2, N);
}